// round 1
// baseline (speedup 1.0000x reference)
#include <cuda_runtime.h>

// Problem constants
#define BB 8
#define HH 128
#define WW 128
#define CC 16
#define HID 256
#define NL 3
#define STEPS 16
#define NELEM (BB*HH*WW*CC)   // 2,097,152

// SMEM layout (in floats)
//  halo : 10*10*16        = 1600
//  p    : 64*16           = 1024
//  cw   : 16*16*9         = 2304
//  A    : 64*260          = 16640
//  Bact : 64*260          = 16640
//  W    : 256*33          = 8448
#define OFF_HALO 0
#define OFF_P    1600
#define OFF_CW   2624
#define OFF_A    4928
#define OFF_B    21568
#define OFF_W    38208
#define SMEM_FLOATS 46656
#define SMEM_BYTES (SMEM_FLOATS*4)   // 186,624 B

#define ACT_PITCH 260

__global__ __launch_bounds__(256, 1)
void nca_step_kernel(const float* __restrict__ hin, float* __restrict__ hout,
                     const float* __restrict__ conv_w,
                     const float* __restrict__ w_first,
                     const float* __restrict__ b_first,
                     const float* __restrict__ w_interim,
                     const float* __restrict__ b_interim,
                     const float* __restrict__ w_last)
{
    extern __shared__ float sm[];
    float* smHalo = sm + OFF_HALO;
    float* smP    = sm + OFF_P;
    float* smCw   = sm + OFF_CW;
    float* smA    = sm + OFF_A;
    float* smB    = sm + OFF_B;
    float* smW    = sm + OFF_W;

    const int tid = threadIdx.x;
    const int x0 = blockIdx.x * 8;
    const int y0 = blockIdx.y * 8;
    const int b  = blockIdx.z;
    const float* hbase = hin + (size_t)b * HH * WW * CC;

    // ---- Load halo (10x10x16, zero padded) + conv weights ----
    for (int f = tid; f < 1600; f += 256) {
        int c  = f & 15;
        int xx = (f >> 4) % 10;
        int yy = f / 160;
        int gy = y0 - 1 + yy;
        int gx = x0 - 1 + xx;
        float v = 0.f;
        if (gy >= 0 && gy < HH && gx >= 0 && gx < WW)
            v = hbase[((size_t)gy * WW + gx) * CC + c];
        smHalo[f] = v;
    }
    for (int f = tid; f < 2304; f += 256) smCw[f] = conv_w[f];
    __syncthreads();

    // ---- Conv 3x3 (torch transpose semantics: W[o][i][r][s], r shifts x, s shifts y) ----
    // p[y][x][o] = sum_{i,r,s} h[y+s-1][x+r-1][i] * cw[o][i][r][s]
    {
        const int m  = tid & 63;
        const int og = tid >> 6;          // 4 output channels per thread
        const int ly = m >> 3, lx = m & 7;
        float a0 = 0.f, a1 = 0.f, a2 = 0.f, a3 = 0.f;
        #pragma unroll
        for (int ci = 0; ci < 16; ci++) {
            #pragma unroll
            for (int r = 0; r < 3; r++) {
                #pragma unroll
                for (int s = 0; s < 3; s++) {
                    float hv = smHalo[((ly + s) * 10 + (lx + r)) * 16 + ci];
                    int cb = og * 576 + ci * 9 + r * 3 + s;
                    a0 = fmaf(hv, smCw[cb      ], a0);
                    a1 = fmaf(hv, smCw[cb + 144], a1);
                    a2 = fmaf(hv, smCw[cb + 288], a2);
                    a3 = fmaf(hv, smCw[cb + 432], a3);
                }
            }
        }
        smP[m * 16 + og * 4 + 0] = a0;
        smP[m * 16 + og * 4 + 1] = a1;
        smP[m * 16 + og * 4 + 2] = a2;
        smP[m * 16 + og * 4 + 3] = a3;
    }
    __syncthreads();

    // ---- Layer 1: 16 -> 256, relu. Thread tid owns output column n=tid. ----
    {
        const int n = tid;
        const float4 w0 = *(const float4*)(w_first + n * 16 + 0);
        const float4 w1 = *(const float4*)(w_first + n * 16 + 4);
        const float4 w2 = *(const float4*)(w_first + n * 16 + 8);
        const float4 w3 = *(const float4*)(w_first + n * 16 + 12);
        const float bias = b_first[n];
        #pragma unroll
        for (int m = 0; m < 64; m++) {
            const float4* pr = (const float4*)(smP + m * 16);
            float4 p0 = pr[0], p1 = pr[1], p2 = pr[2], p3 = pr[3];
            float a = bias;
            a = fmaf(p0.x, w0.x, a); a = fmaf(p0.y, w0.y, a);
            a = fmaf(p0.z, w0.z, a); a = fmaf(p0.w, w0.w, a);
            a = fmaf(p1.x, w1.x, a); a = fmaf(p1.y, w1.y, a);
            a = fmaf(p1.z, w1.z, a); a = fmaf(p1.w, w1.w, a);
            a = fmaf(p2.x, w2.x, a); a = fmaf(p2.y, w2.y, a);
            a = fmaf(p2.z, w2.z, a); a = fmaf(p2.w, w2.w, a);
            a = fmaf(p3.x, w3.x, a); a = fmaf(p3.y, w3.y, a);
            a = fmaf(p3.z, w3.z, a); a = fmaf(p3.w, w3.w, a);
            smA[m * ACT_PITCH + n] = fmaxf(a, 0.f);
        }
    }
    // (no sync needed here: interim layer 0 begins with a sync before panel load)

    // ---- Interim layers: 3 x (256 -> 256, relu). Ping-pong smA <-> smB. ----
    const float* smIn = smA;
    float*       smOut = smB;
    for (int l = 0; l < NL; l++) {
        const float* Wl = w_interim + l * HID * HID;
        const int n = tid;
        const float bias = b_interim[l * HID + n];
        float acc[64];
        #pragma unroll
        for (int m = 0; m < 64; m++) acc[m] = bias;

        for (int k0 = 0; k0 < HID; k0 += 32) {
            __syncthreads();   // previous panel fully consumed / prev layer done
            // Stage weight panel: W[n][k0..k0+31] -> smW[n*33 + kk] (conflict-free)
            #pragma unroll
            for (int j = 0; j < 32; j++) {
                int f  = tid + 256 * j;
                int nn = f >> 5;
                int kk = f & 31;
                smW[nn * 33 + kk] = Wl[nn * HID + k0 + kk];
            }
            __syncthreads();

            #pragma unroll 1
            for (int kk = 0; kk < 32; kk += 4) {
                const float w0 = smW[n * 33 + kk + 0];
                const float w1 = smW[n * 33 + kk + 1];
                const float w2 = smW[n * 33 + kk + 2];
                const float w3 = smW[n * 33 + kk + 3];
                const float* ain = smIn + k0 + kk;
                #pragma unroll
                for (int m = 0; m < 64; m++) {
                    float4 a4 = *(const float4*)(ain + m * ACT_PITCH); // broadcast
                    acc[m] = fmaf(a4.x, w0, acc[m]);
                    acc[m] = fmaf(a4.y, w1, acc[m]);
                    acc[m] = fmaf(a4.z, w2, acc[m]);
                    acc[m] = fmaf(a4.w, w3, acc[m]);
                }
            }
        }
        // Safe to write smOut: it was last read a full layer ago (sync-protected).
        #pragma unroll
        for (int m = 0; m < 64; m++)
            smOut[m * ACT_PITCH + n] = fmaxf(acc[m], 0.f);
        // swap
        float* t = (float*)smIn; smIn = smOut; smOut = t;
    }
    // After L1->A, l0:A->B, l1:B->A, l2:A->B  => smIn == smB holds the final acts.

    __syncthreads();   // all threads done with smW panels and finished writing smIn
    // ---- Last layer: 256 -> 16 (no bias) + residual + store ----
    for (int f = tid; f < 4096; f += 256) smW[f] = w_last[f];
    __syncthreads();
    {
        const int m  = tid >> 2;   // cell
        const int kg = tid & 3;    // k-partition (64 each)
        float acc[16];
        #pragma unroll
        for (int co = 0; co < 16; co++) acc[co] = 0.f;
        const float* arow = smIn + m * ACT_PITCH + kg * 64;
        #pragma unroll 1
        for (int k = 0; k < 64; k += 4) {
            float4 a4 = *(const float4*)(arow + k);
            #pragma unroll
            for (int co = 0; co < 16; co++) {
                float4 w4 = *(const float4*)(smW + co * 256 + kg * 64 + k);
                acc[co] = fmaf(a4.x, w4.x, acc[co]);
                acc[co] = fmaf(a4.y, w4.y, acc[co]);
                acc[co] = fmaf(a4.z, w4.z, acc[co]);
                acc[co] = fmaf(a4.w, w4.w, acc[co]);
            }
        }
        // reduce over the 4 k-partitions (lanes tid, tid^1, tid^2 share a cell)
        #pragma unroll
        for (int co = 0; co < 16; co++) {
            acc[co] += __shfl_xor_sync(0xffffffffu, acc[co], 1);
            acc[co] += __shfl_xor_sync(0xffffffffu, acc[co], 2);
        }
        const int ly = m >> 3, lx = m & 7;
        const int gy = y0 + ly, gx = x0 + lx;
        float* dst = hout + (((size_t)b * HH + gy) * WW + gx) * CC;
        const float* hold = smHalo + ((ly + 1) * 10 + (lx + 1)) * 16;
        #pragma unroll
        for (int j = 0; j < 4; j++) {
            int co = kg * 4 + j;
            dst[co] = hold[co] + acc[co];
        }
    }
}

__global__ void copy_f4_kernel(const float4* __restrict__ src, float4* __restrict__ dst)
{
    int i = blockIdx.x * blockDim.x + threadIdx.x;
    dst[i] = src[i];
}

extern "C" void kernel_launch(void* const* d_in, const int* in_sizes, int n_in,
                              void* d_out, int out_size)
{
    const float* x         = (const float*)d_in[0];
    const float* conv_w    = (const float*)d_in[1];
    const float* w_first   = (const float*)d_in[2];
    const float* b_first   = (const float*)d_in[3];
    const float* w_interim = (const float*)d_in[4];
    const float* b_interim = (const float*)d_in[5];
    const float* w_last    = (const float*)d_in[6];
    // d_in[7] (steps) unused: fixed at 16 by the problem setup.

    float* out  = (float*)d_out;            // x_final: NELEM floats
    float* hist = out + NELEM;              // history: (STEPS+1) * NELEM floats

    cudaFuncSetAttribute(nca_step_kernel,
                         cudaFuncAttributeMaxDynamicSharedMemorySize, SMEM_BYTES);

    // history[0] = x
    copy_f4_kernel<<<NELEM / 4 / 256, 256>>>((const float4*)x, (float4*)hist);

    dim3 grid(WW / 8, HH / 8, BB);
    for (int t = 1; t <= STEPS; t++) {
        nca_step_kernel<<<grid, 256, SMEM_BYTES>>>(
            hist + (size_t)(t - 1) * NELEM,
            hist + (size_t)t * NELEM,
            conv_w, w_first, b_first, w_interim, b_interim, w_last);
    }

    // x_final = history[STEPS]
    copy_f4_kernel<<<NELEM / 4 / 256, 256>>>(
        (const float4*)(hist + (size_t)STEPS * NELEM), (float4*)out);
}

// round 2
// speedup vs baseline: 1.0007x; 1.0007x over previous
#include <cuda_runtime.h>

// Problem constants
#define BB 8
#define HH 128
#define WW 128
#define CC 16
#define HID 256
#define NL 3
#define STEPS 16
#define NELEM (BB*HH*WW*CC)   // 2,097,152

// SMEM layout (in floats)
//  halo : 10*10*16        = 1600
//  p    : 64*16           = 1024
//  cw   : 16*16*9         = 2304
//  A    : 64*260          = 16640
//  Bact : 64*260          = 16640
//  W    : 256*33          = 8448
#define OFF_HALO 0
#define OFF_P    1600
#define OFF_CW   2624
#define OFF_A    4928
#define OFF_B    21568
#define OFF_W    38208
#define SMEM_FLOATS 46656
#define SMEM_BYTES (SMEM_FLOATS*4)   // 186,624 B

#define ACT_PITCH 260

__global__ __launch_bounds__(256, 1)
void nca_step_kernel(const float* __restrict__ hin, float* __restrict__ hout,
                     const float* __restrict__ conv_w,
                     const float* __restrict__ w_first,
                     const float* __restrict__ b_first,
                     const float* __restrict__ w_interim,
                     const float* __restrict__ b_interim,
                     const float* __restrict__ w_last)
{
    extern __shared__ float sm[];
    float* smHalo = sm + OFF_HALO;
    float* smP    = sm + OFF_P;
    float* smCw   = sm + OFF_CW;
    float* smA    = sm + OFF_A;
    float* smB    = sm + OFF_B;
    float* smW    = sm + OFF_W;

    const int tid = threadIdx.x;
    const int x0 = blockIdx.x * 8;
    const int y0 = blockIdx.y * 8;
    const int b  = blockIdx.z;
    const float* hbase = hin + (size_t)b * HH * WW * CC;

    // ---- Load halo (10x10x16, zero padded) + conv weights ----
    for (int f = tid; f < 1600; f += 256) {
        int c  = f & 15;
        int xx = (f >> 4) % 10;
        int yy = f / 160;
        int gy = y0 - 1 + yy;
        int gx = x0 - 1 + xx;
        float v = 0.f;
        if (gy >= 0 && gy < HH && gx >= 0 && gx < WW)
            v = hbase[((size_t)gy * WW + gx) * CC + c];
        smHalo[f] = v;
    }
    for (int f = tid; f < 2304; f += 256) smCw[f] = conv_w[f];
    __syncthreads();

    // ---- Conv 3x3 (torch transpose semantics: W[o][i][r][s], r shifts x, s shifts y) ----
    // p[y][x][o] = sum_{i,r,s} h[y+s-1][x+r-1][i] * cw[o][i][r][s]
    {
        const int m  = tid & 63;
        const int og = tid >> 6;          // 4 output channels per thread
        const int ly = m >> 3, lx = m & 7;
        float a0 = 0.f, a1 = 0.f, a2 = 0.f, a3 = 0.f;
        #pragma unroll
        for (int ci = 0; ci < 16; ci++) {
            #pragma unroll
            for (int r = 0; r < 3; r++) {
                #pragma unroll
                for (int s = 0; s < 3; s++) {
                    float hv = smHalo[((ly + s) * 10 + (lx + r)) * 16 + ci];
                    int cb = og * 576 + ci * 9 + r * 3 + s;
                    a0 = fmaf(hv, smCw[cb      ], a0);
                    a1 = fmaf(hv, smCw[cb + 144], a1);
                    a2 = fmaf(hv, smCw[cb + 288], a2);
                    a3 = fmaf(hv, smCw[cb + 432], a3);
                }
            }
        }
        smP[m * 16 + og * 4 + 0] = a0;
        smP[m * 16 + og * 4 + 1] = a1;
        smP[m * 16 + og * 4 + 2] = a2;
        smP[m * 16 + og * 4 + 3] = a3;
    }
    __syncthreads();

    // ---- Layer 1: 16 -> 256, relu. Thread tid owns output column n=tid. ----
    {
        const int n = tid;
        const float4 w0 = *(const float4*)(w_first + n * 16 + 0);
        const float4 w1 = *(const float4*)(w_first + n * 16 + 4);
        const float4 w2 = *(const float4*)(w_first + n * 16 + 8);
        const float4 w3 = *(const float4*)(w_first + n * 16 + 12);
        const float bias = b_first[n];
        #pragma unroll
        for (int m = 0; m < 64; m++) {
            const float4* pr = (const float4*)(smP + m * 16);
            float4 p0 = pr[0], p1 = pr[1], p2 = pr[2], p3 = pr[3];
            float a = bias;
            a = fmaf(p0.x, w0.x, a); a = fmaf(p0.y, w0.y, a);
            a = fmaf(p0.z, w0.z, a); a = fmaf(p0.w, w0.w, a);
            a = fmaf(p1.x, w1.x, a); a = fmaf(p1.y, w1.y, a);
            a = fmaf(p1.z, w1.z, a); a = fmaf(p1.w, w1.w, a);
            a = fmaf(p2.x, w2.x, a); a = fmaf(p2.y, w2.y, a);
            a = fmaf(p2.z, w2.z, a); a = fmaf(p2.w, w2.w, a);
            a = fmaf(p3.x, w3.x, a); a = fmaf(p3.y, w3.y, a);
            a = fmaf(p3.z, w3.z, a); a = fmaf(p3.w, w3.w, a);
            smA[m * ACT_PITCH + n] = fmaxf(a, 0.f);
        }
    }
    // (no sync needed here: interim layer 0 begins with a sync before panel load)

    // ---- Interim layers: 3 x (256 -> 256, relu). Ping-pong smA <-> smB. ----
    const float* smIn = smA;
    float*       smOut = smB;
    for (int l = 0; l < NL; l++) {
        const float* Wl = w_interim + l * HID * HID;
        const int n = tid;
        const float bias = b_interim[l * HID + n];
        float acc[64];
        #pragma unroll
        for (int m = 0; m < 64; m++) acc[m] = bias;

        for (int k0 = 0; k0 < HID; k0 += 32) {
            __syncthreads();   // previous panel fully consumed / prev layer done
            // Stage weight panel: W[n][k0..k0+31] -> smW[n*33 + kk] (conflict-free)
            #pragma unroll
            for (int j = 0; j < 32; j++) {
                int f  = tid + 256 * j;
                int nn = f >> 5;
                int kk = f & 31;
                smW[nn * 33 + kk] = Wl[nn * HID + k0 + kk];
            }
            __syncthreads();

            #pragma unroll 1
            for (int kk = 0; kk < 32; kk += 4) {
                const float w0 = smW[n * 33 + kk + 0];
                const float w1 = smW[n * 33 + kk + 1];
                const float w2 = smW[n * 33 + kk + 2];
                const float w3 = smW[n * 33 + kk + 3];
                const float* ain = smIn + k0 + kk;
                #pragma unroll
                for (int m = 0; m < 64; m++) {
                    float4 a4 = *(const float4*)(ain + m * ACT_PITCH); // broadcast
                    acc[m] = fmaf(a4.x, w0, acc[m]);
                    acc[m] = fmaf(a4.y, w1, acc[m]);
                    acc[m] = fmaf(a4.z, w2, acc[m]);
                    acc[m] = fmaf(a4.w, w3, acc[m]);
                }
            }
        }
        // Safe to write smOut: it was last read a full layer ago (sync-protected).
        #pragma unroll
        for (int m = 0; m < 64; m++)
            smOut[m * ACT_PITCH + n] = fmaxf(acc[m], 0.f);
        // swap
        float* t = (float*)smIn; smIn = smOut; smOut = t;
    }
    // After L1->A, l0:A->B, l1:B->A, l2:A->B  => smIn == smB holds the final acts.

    __syncthreads();   // all threads done with smW panels and finished writing smIn
    // ---- Last layer: 256 -> 16 (no bias) + residual + store ----
    for (int f = tid; f < 4096; f += 256) smW[f] = w_last[f];
    __syncthreads();
    {
        const int m  = tid >> 2;   // cell
        const int kg = tid & 3;    // k-partition (64 each)
        float acc[16];
        #pragma unroll
        for (int co = 0; co < 16; co++) acc[co] = 0.f;
        const float* arow = smIn + m * ACT_PITCH + kg * 64;
        #pragma unroll 1
        for (int k = 0; k < 64; k += 4) {
            float4 a4 = *(const float4*)(arow + k);
            #pragma unroll
            for (int co = 0; co < 16; co++) {
                float4 w4 = *(const float4*)(smW + co * 256 + kg * 64 + k);
                acc[co] = fmaf(a4.x, w4.x, acc[co]);
                acc[co] = fmaf(a4.y, w4.y, acc[co]);
                acc[co] = fmaf(a4.z, w4.z, acc[co]);
                acc[co] = fmaf(a4.w, w4.w, acc[co]);
            }
        }
        // reduce over the 4 k-partitions (lanes tid, tid^1, tid^2 share a cell)
        #pragma unroll
        for (int co = 0; co < 16; co++) {
            acc[co] += __shfl_xor_sync(0xffffffffu, acc[co], 1);
            acc[co] += __shfl_xor_sync(0xffffffffu, acc[co], 2);
        }
        const int ly = m >> 3, lx = m & 7;
        const int gy = y0 + ly, gx = x0 + lx;
        float* dst = hout + (((size_t)b * HH + gy) * WW + gx) * CC;
        const float* hold = smHalo + ((ly + 1) * 10 + (lx + 1)) * 16;
        #pragma unroll
        for (int j = 0; j < 4; j++) {
            int co = kg * 4 + j;
            dst[co] = hold[co] + acc[co];
        }
    }
}

__global__ void copy_f4_kernel(const float4* __restrict__ src, float4* __restrict__ dst)
{
    int i = blockIdx.x * blockDim.x + threadIdx.x;
    dst[i] = src[i];
}

extern "C" void kernel_launch(void* const* d_in, const int* in_sizes, int n_in,
                              void* d_out, int out_size)
{
    const float* x         = (const float*)d_in[0];
    const float* conv_w    = (const float*)d_in[1];
    const float* w_first   = (const float*)d_in[2];
    const float* b_first   = (const float*)d_in[3];
    const float* w_interim = (const float*)d_in[4];
    const float* b_interim = (const float*)d_in[5];
    const float* w_last    = (const float*)d_in[6];
    // d_in[7] (steps) unused: fixed at 16 by the problem setup.

    float* out  = (float*)d_out;            // x_final: NELEM floats
    float* hist = out + NELEM;              // history: (STEPS+1) * NELEM floats

    cudaFuncSetAttribute(nca_step_kernel,
                         cudaFuncAttributeMaxDynamicSharedMemorySize, SMEM_BYTES);

    // history[0] = x
    copy_f4_kernel<<<NELEM / 4 / 256, 256>>>((const float4*)x, (float4*)hist);

    dim3 grid(WW / 8, HH / 8, BB);
    for (int t = 1; t <= STEPS; t++) {
        nca_step_kernel<<<grid, 256, SMEM_BYTES>>>(
            hist + (size_t)(t - 1) * NELEM,
            hist + (size_t)t * NELEM,
            conv_w, w_first, b_first, w_interim, b_interim, w_last);
    }

    // x_final = history[STEPS]
    copy_f4_kernel<<<NELEM / 4 / 256, 256>>>(
        (const float4*)(hist + (size_t)STEPS * NELEM), (float4*)out);
}

// round 3
// speedup vs baseline: 2.3503x; 2.3487x over previous
#include <cuda_runtime.h>
#include <cstdint>

// Problem constants
#define BB 8
#define HH 128
#define WW 128
#define CC 16
#define HID 256
#define NL 3
#define STEPS 16
#define NELEM (BB*HH*WW*CC)   // 2,097,152

// SMEM layout (in floats)
//  halo : 10*10*16        = 1600
//  p    : 64*16           = 1024
//  cw   : 16*16*9         = 2304
//  A    : 64*260          = 16640
//  Bact : 64*260          = 16640
//  W    : 256*36          = 9216   (tf32 weight panel, pitch 36 -> conflict-free frags)
#define OFF_HALO 0
#define OFF_P    1600
#define OFF_CW   2624
#define OFF_A    4928
#define OFF_B    21568
#define OFF_W    38208
#define SMEM_FLOATS 47424
#define SMEM_BYTES (SMEM_FLOATS*4)   // 189,696 B

#define ACT_PITCH 260
#define WP 36   // weight panel pitch (== 4 mod 32 -> bank-conflict-free fragment loads)

__device__ __forceinline__ float tf32r(float x) {
    uint32_t u;
    asm("cvt.rna.tf32.f32 %0, %1;" : "=r"(u) : "f"(x));
    return __uint_as_float(u);
}

__device__ __forceinline__ void mma_tf32(float* c, const uint32_t* a, const uint32_t* b) {
    asm volatile(
        "mma.sync.aligned.m16n8k8.row.col.f32.tf32.tf32.f32 "
        "{%0,%1,%2,%3}, {%4,%5,%6,%7}, {%8,%9}, {%0,%1,%2,%3};\n"
        : "+f"(c[0]), "+f"(c[1]), "+f"(c[2]), "+f"(c[3])
        : "r"(a[0]), "r"(a[1]), "r"(a[2]), "r"(a[3]), "r"(b[0]), "r"(b[1]));
}

__global__ __launch_bounds__(256, 1)
void nca_step_kernel(const float* __restrict__ hin, float* __restrict__ hout,
                     const float* __restrict__ conv_w,
                     const float* __restrict__ w_first,
                     const float* __restrict__ b_first,
                     const float* __restrict__ w_interim,
                     const float* __restrict__ b_interim,
                     const float* __restrict__ w_last)
{
    extern __shared__ float sm[];
    float* smHalo = sm + OFF_HALO;
    float* smP    = sm + OFF_P;
    float* smCw   = sm + OFF_CW;
    float* smA    = sm + OFF_A;
    float* smB    = sm + OFF_B;
    float* smW    = sm + OFF_W;

    const int tid = threadIdx.x;
    const int x0 = blockIdx.x * 8;
    const int y0 = blockIdx.y * 8;
    const int b  = blockIdx.z;
    const float* hbase = hin + (size_t)b * HH * WW * CC;

    // ---- Load halo (10x10x16, zero padded) + conv weights ----
    for (int f = tid; f < 1600; f += 256) {
        int c  = f & 15;
        int xx = (f >> 4) % 10;
        int yy = f / 160;
        int gy = y0 - 1 + yy;
        int gx = x0 - 1 + xx;
        float v = 0.f;
        if (gy >= 0 && gy < HH && gx >= 0 && gx < WW)
            v = hbase[((size_t)gy * WW + gx) * CC + c];
        smHalo[f] = v;
    }
    for (int f = tid; f < 2304; f += 256) smCw[f] = conv_w[f];
    __syncthreads();

    // ---- Conv 3x3 (torch transpose semantics) ----
    {
        const int m  = tid & 63;
        const int og = tid >> 6;          // 4 output channels per thread
        const int ly = m >> 3, lx = m & 7;
        float a0 = 0.f, a1 = 0.f, a2 = 0.f, a3 = 0.f;
        #pragma unroll
        for (int ci = 0; ci < 16; ci++) {
            #pragma unroll
            for (int r = 0; r < 3; r++) {
                #pragma unroll
                for (int s = 0; s < 3; s++) {
                    float hv = smHalo[((ly + s) * 10 + (lx + r)) * 16 + ci];
                    int cb = og * 576 + ci * 9 + r * 3 + s;
                    a0 = fmaf(hv, smCw[cb      ], a0);
                    a1 = fmaf(hv, smCw[cb + 144], a1);
                    a2 = fmaf(hv, smCw[cb + 288], a2);
                    a3 = fmaf(hv, smCw[cb + 432], a3);
                }
            }
        }
        smP[m * 16 + og * 4 + 0] = a0;
        smP[m * 16 + og * 4 + 1] = a1;
        smP[m * 16 + og * 4 + 2] = a2;
        smP[m * 16 + og * 4 + 3] = a3;
    }
    __syncthreads();

    // ---- Layer 1: 16 -> 256, relu, fp32 FFMA. Thread tid owns output column n=tid. ----
    {
        const int n = tid;
        const float4 w0 = *(const float4*)(w_first + n * 16 + 0);
        const float4 w1 = *(const float4*)(w_first + n * 16 + 4);
        const float4 w2 = *(const float4*)(w_first + n * 16 + 8);
        const float4 w3 = *(const float4*)(w_first + n * 16 + 12);
        const float bias = b_first[n];
        #pragma unroll
        for (int m = 0; m < 64; m++) {
            const float4* pr = (const float4*)(smP + m * 16);
            float4 p0 = pr[0], p1 = pr[1], p2 = pr[2], p3 = pr[3];
            float a = bias;
            a = fmaf(p0.x, w0.x, a); a = fmaf(p0.y, w0.y, a);
            a = fmaf(p0.z, w0.z, a); a = fmaf(p0.w, w0.w, a);
            a = fmaf(p1.x, w1.x, a); a = fmaf(p1.y, w1.y, a);
            a = fmaf(p1.z, w1.z, a); a = fmaf(p1.w, w1.w, a);
            a = fmaf(p2.x, w2.x, a); a = fmaf(p2.y, w2.y, a);
            a = fmaf(p2.z, w2.z, a); a = fmaf(p2.w, w2.w, a);
            a = fmaf(p3.x, w3.x, a); a = fmaf(p3.y, w3.y, a);
            a = fmaf(p3.z, w3.z, a); a = fmaf(p3.w, w3.w, a);
            // tf32-round at store: next consumer is the tensor-core layer
            smA[m * ACT_PITCH + n] = tf32r(fmaxf(a, 0.f));
        }
    }

    // ---- Interim layers: 3 x (256 -> 256, relu) via tf32 mma.sync ----
    // Warp tile: 32(M) x 64(N) = 2 x 8 m16n8k8 tiles.
    const int lane = tid & 31;
    const int wid  = tid >> 5;
    const int g = lane >> 2;        // groupID
    const int t = lane & 3;         // threadID_in_group
    const int m0 = (wid & 1) * 32;  // warp m offset
    const int n0 = (wid >> 1) * 64; // warp n offset

    const float* smIn = smA;
    float*       smOut = smB;
    for (int l = 0; l < NL; l++) {
        const float* Wl = w_interim + l * HID * HID;

        float acc[2][8][4];
        #pragma unroll
        for (int nt = 0; nt < 8; nt++) {
            float bz0 = b_interim[l * HID + n0 + nt * 8 + 2 * t];
            float bz1 = b_interim[l * HID + n0 + nt * 8 + 2 * t + 1];
            #pragma unroll
            for (int mt = 0; mt < 2; mt++) {
                acc[mt][nt][0] = bz0; acc[mt][nt][1] = bz1;
                acc[mt][nt][2] = bz0; acc[mt][nt][3] = bz1;
            }
        }

        for (int k0 = 0; k0 < HID; k0 += 32) {
            __syncthreads();   // previous panel fully consumed (and, at k0==0, prev layer done)
            // Stage weight panel: W[n][k0..k0+31] -> smW[n*WP + kk], tf32-rounded
            #pragma unroll
            for (int j = 0; j < 32; j++) {
                int f  = tid + 256 * j;
                int nn = f >> 5;
                int kk = f & 31;
                smW[nn * WP + kk] = tf32r(Wl[nn * HID + k0 + kk]);
            }
            __syncthreads();

            #pragma unroll
            for (int ks = 0; ks < 32; ks += 8) {
                const int kg = k0 + ks;
                uint32_t afr[2][4];
                #pragma unroll
                for (int mt = 0; mt < 2; mt++) {
                    const int r0 = m0 + mt * 16 + g;
                    afr[mt][0] = __float_as_uint(smIn[ r0      * ACT_PITCH + kg + t    ]);
                    afr[mt][1] = __float_as_uint(smIn[(r0 + 8) * ACT_PITCH + kg + t    ]);
                    afr[mt][2] = __float_as_uint(smIn[ r0      * ACT_PITCH + kg + t + 4]);
                    afr[mt][3] = __float_as_uint(smIn[(r0 + 8) * ACT_PITCH + kg + t + 4]);
                }
                uint32_t bfr[8][2];
                #pragma unroll
                for (int nt = 0; nt < 8; nt++) {
                    const int n = n0 + nt * 8 + g;
                    bfr[nt][0] = __float_as_uint(smW[n * WP + ks + t    ]);
                    bfr[nt][1] = __float_as_uint(smW[n * WP + ks + t + 4]);
                }
                #pragma unroll
                for (int mt = 0; mt < 2; mt++)
                    #pragma unroll
                    for (int nt = 0; nt < 8; nt++)
                        mma_tf32(acc[mt][nt], afr[mt], bfr[nt]);
            }
        }

        // relu + tf32-round + store (smOut != smIn and != smW: no race)
        #pragma unroll
        for (int mt = 0; mt < 2; mt++) {
            #pragma unroll
            for (int nt = 0; nt < 8; nt++) {
                const int r0 = m0 + mt * 16 + g;
                const int n  = n0 + nt * 8 + 2 * t;
                float2 lo, hi;
                lo.x = tf32r(fmaxf(acc[mt][nt][0], 0.f));
                lo.y = tf32r(fmaxf(acc[mt][nt][1], 0.f));
                hi.x = tf32r(fmaxf(acc[mt][nt][2], 0.f));
                hi.y = tf32r(fmaxf(acc[mt][nt][3], 0.f));
                *(float2*)(smOut +  r0      * ACT_PITCH + n) = lo;
                *(float2*)(smOut + (r0 + 8) * ACT_PITCH + n) = hi;
            }
        }
        // swap
        float* tmp = (float*)smIn; smIn = smOut; smOut = tmp;
    }
    // L1->A, l0:A->B, l1:B->A, l2:A->B  => smIn == smB holds the final acts.

    __syncthreads();   // all warps done with panels & finished writing smIn
    // ---- Last layer: 256 -> 16 (no bias) + residual + store, fp32 FFMA ----
    for (int f = tid; f < 4096; f += 256) smW[f] = w_last[f];
    __syncthreads();
    {
        const int m  = tid >> 2;   // cell
        const int kg2 = tid & 3;   // k-partition (64 each)
        float acc2[16];
        #pragma unroll
        for (int co = 0; co < 16; co++) acc2[co] = 0.f;
        const float* arow = smIn + m * ACT_PITCH + kg2 * 64;
        #pragma unroll 1
        for (int k = 0; k < 64; k += 4) {
            float4 a4 = *(const float4*)(arow + k);
            #pragma unroll
            for (int co = 0; co < 16; co++) {
                float4 w4 = *(const float4*)(smW + co * 256 + kg2 * 64 + k);
                acc2[co] = fmaf(a4.x, w4.x, acc2[co]);
                acc2[co] = fmaf(a4.y, w4.y, acc2[co]);
                acc2[co] = fmaf(a4.z, w4.z, acc2[co]);
                acc2[co] = fmaf(a4.w, w4.w, acc2[co]);
            }
        }
        #pragma unroll
        for (int co = 0; co < 16; co++) {
            acc2[co] += __shfl_xor_sync(0xffffffffu, acc2[co], 1);
            acc2[co] += __shfl_xor_sync(0xffffffffu, acc2[co], 2);
        }
        const int ly = m >> 3, lx = m & 7;
        const int gy = y0 + ly, gx = x0 + lx;
        float* dst = hout + (((size_t)b * HH + gy) * WW + gx) * CC;
        const float* hold = smHalo + ((ly + 1) * 10 + (lx + 1)) * 16;
        #pragma unroll
        for (int j = 0; j < 4; j++) {
            int co = kg2 * 4 + j;
            dst[co] = hold[co] + acc2[co];
        }
    }
}

__global__ void copy_f4_kernel(const float4* __restrict__ src, float4* __restrict__ dst)
{
    int i = blockIdx.x * blockDim.x + threadIdx.x;
    dst[i] = src[i];
}

extern "C" void kernel_launch(void* const* d_in, const int* in_sizes, int n_in,
                              void* d_out, int out_size)
{
    const float* x         = (const float*)d_in[0];
    const float* conv_w    = (const float*)d_in[1];
    const float* w_first   = (const float*)d_in[2];
    const float* b_first   = (const float*)d_in[3];
    const float* w_interim = (const float*)d_in[4];
    const float* b_interim = (const float*)d_in[5];
    const float* w_last    = (const float*)d_in[6];
    // d_in[7] (steps) unused: fixed at 16 by the problem setup.

    float* out  = (float*)d_out;            // x_final: NELEM floats
    float* hist = out + NELEM;              // history: (STEPS+1) * NELEM floats

    cudaFuncSetAttribute(nca_step_kernel,
                         cudaFuncAttributeMaxDynamicSharedMemorySize, SMEM_BYTES);

    // history[0] = x
    copy_f4_kernel<<<NELEM / 4 / 256, 256>>>((const float4*)x, (float4*)hist);

    dim3 grid(WW / 8, HH / 8, BB);
    for (int t = 1; t <= STEPS; t++) {
        nca_step_kernel<<<grid, 256, SMEM_BYTES>>>(
            hist + (size_t)(t - 1) * NELEM,
            hist + (size_t)t * NELEM,
            conv_w, w_first, b_first, w_interim, b_interim, w_last);
    }

    // x_final = history[STEPS]
    copy_f4_kernel<<<NELEM / 4 / 256, 256>>>(
        (const float4*)(hist + (size_t)STEPS * NELEM), (float4*)out);
}

// round 4
// speedup vs baseline: 2.9469x; 1.2539x over previous
#include <cuda_runtime.h>
#include <cstdint>

// Problem constants
#define BB 8
#define HH 128
#define WW 128
#define CC 16
#define HID 256
#define NL 3
#define STEPS 16
#define NELEM (BB*HH*WW*CC)   // 2,097,152

// SMEM layout (floats)
#define OFF_HALO 0            // 10*10*16 = 1600
#define OFF_CW   1600         // 16*16*9  = 2304
#define OFF_ACTA 3904         // 4mt*32kt*32lane*4 = 16384
#define OFF_ACTB 20288        // 16384  (also holds P frag [4mt][2kt][32][4] early)
#define OFF_WBUF 36672        // 2 * 8192 (double-buffered weight panel)
#define SMEM_FLOATS 53056
#define SMEM_BYTES (SMEM_FLOATS*4)   // 212,224 B

// Pre-swizzled weights in gmem (written once per launch by preswizzle_kernel)
#define WSWZ_FIRST 196608     // 4096 floats
#define WSWZ_LAST  200704     // 4096 floats
__device__ float g_wswz[204800];

__device__ __forceinline__ float tf32r(float x) {
    uint32_t u;
    asm("cvt.rna.tf32.f32 %0, %1;" : "=r"(u) : "f"(x));
    return __uint_as_float(u);
}

__device__ __forceinline__ void mma8(float* c, const float4& a, float b0, float b1) {
    asm volatile(
        "mma.sync.aligned.m16n8k8.row.col.f32.tf32.tf32.f32 "
        "{%0,%1,%2,%3}, {%4,%5,%6,%7}, {%8,%9}, {%0,%1,%2,%3};\n"
        : "+f"(c[0]), "+f"(c[1]), "+f"(c[2]), "+f"(c[3])
        : "r"(__float_as_uint(a.x)), "r"(__float_as_uint(a.y)),
          "r"(__float_as_uint(a.z)), "r"(__float_as_uint(a.w)),
          "r"(__float_as_uint(b0)),  "r"(__float_as_uint(b1)));
}

__device__ __forceinline__ void cpa16(uint32_t dst, const float* src) {
    asm volatile("cp.async.cg.shared.global [%0], [%1], 16;\n" :: "r"(dst), "l"(src));
}
__device__ __forceinline__ void cpa_commit() { asm volatile("cp.async.commit_group;\n" ::: "memory"); }
__device__ __forceinline__ void cpa_wait0()  { asm volatile("cp.async.wait_group 0;\n"  ::: "memory"); }

// ---------------- Pre-swizzle weights into mma fragment order (tf32) -------------
// interim: idx = ((((l*8+p)*32+nt)*2+kp)*32+lane)*4 + slot
//   value = W_l[n][k], n = nt*8 + (lane>>2), k = p*32 + kp*16 + (lane&3) + 4*(slot&1) + 8*(slot>>1)
// first: idx = WSWZ_FIRST + ((nt*32+lane)*4 + slot), k over 16
// last:  idx = WSWZ_LAST + ((((p*2+ntl)*2+kp)*32+lane)*4 + slot)
__global__ void preswizzle_kernel(const float* __restrict__ wi,
                                  const float* __restrict__ wf,
                                  const float* __restrict__ wl)
{
    int idx = blockIdx.x * blockDim.x + threadIdx.x;
    if (idx >= 204800) return;
    if (idx < WSWZ_FIRST) {
        int slot = idx & 3, lane = (idx >> 2) & 31, kp = (idx >> 7) & 1;
        int nt = (idx >> 8) & 31, p = (idx >> 13) & 7, l = idx >> 16;
        int g = lane >> 2, t = lane & 3;
        int n = nt * 8 + g;
        int k = p * 32 + kp * 16 + t + 4 * (slot & 1) + 8 * (slot >> 1);
        g_wswz[idx] = tf32r(wi[(l * HID + n) * HID + k]);
    } else if (idx < WSWZ_LAST) {
        int j = idx - WSWZ_FIRST;
        int slot = j & 3, lane = (j >> 2) & 31, nt = (j >> 7) & 31;
        int g = lane >> 2, t = lane & 3;
        int n = nt * 8 + g;
        int k = t + 4 * (slot & 1) + 8 * (slot >> 1);
        g_wswz[idx] = tf32r(wf[n * CC + k]);
    } else {
        int j = idx - WSWZ_LAST;
        int slot = j & 3, lane = (j >> 2) & 31, kp = (j >> 7) & 1;
        int ntl = (j >> 8) & 1, p = (j >> 9) & 7;
        int g = lane >> 2, t = lane & 3;
        int n = ntl * 8 + g;
        int k = p * 32 + kp * 16 + t + 4 * (slot & 1) + 8 * (slot >> 1);
        g_wswz[idx] = tf32r(wl[n * HID + k]);
    }
}

// ---------------- Fused NCA step ----------------
__global__ __launch_bounds__(256, 1)
void nca_step_kernel(const float* __restrict__ hin, float* __restrict__ hout,
                     const float* __restrict__ conv_w,
                     const float* __restrict__ b_first,
                     const float* __restrict__ b_interim)
{
    extern __shared__ float sm[];
    float* smHalo = sm + OFF_HALO;
    float* smCw   = sm + OFF_CW;
    float* smActA = sm + OFF_ACTA;
    float* smActB = sm + OFF_ACTB;
    float* smWbuf = sm + OFF_WBUF;
    const uint32_t smWbuf_u = (uint32_t)__cvta_generic_to_shared(smWbuf);

    const int tid = threadIdx.x;
    const int lane = tid & 31;
    const int wid  = tid >> 5;
    const int g = lane >> 2;
    const int t = lane & 3;
    const int mw  = wid & 1;        // warp m-block (2 mtiles each)
    const int n0q = wid >> 1;       // warp n-quarter (8 ntiles each)

    const int x0 = blockIdx.x * 8;
    const int y0 = blockIdx.y * 8;
    const int b  = blockIdx.z;
    const float* hbase = hin + (size_t)b * HH * WW * CC;

    // ---- Prologue: prefetch interim panel 0 -> buf0, w_first -> buf1 ----
    #pragma unroll
    for (int i = 0; i < 8; i++)
        cpa16(smWbuf_u + tid * 128 + i * 16, g_wswz + tid * 32 + i * 4);
    cpa_commit();
    #pragma unroll
    for (int i = 0; i < 4; i++)
        cpa16(smWbuf_u + 8192 * 4 + tid * 64 + i * 16, g_wswz + WSWZ_FIRST + tid * 16 + i * 4);
    cpa_commit();

    // ---- Halo (10x10x16, zero padded) + conv weights ----
    for (int f = tid; f < 1600; f += 256) {
        int c  = f & 15;
        int xx = (f >> 4) % 10;
        int yy = f / 160;
        int gy = y0 - 1 + yy;
        int gx = x0 - 1 + xx;
        float v = 0.f;
        if (gy >= 0 && gy < HH && gx >= 0 && gx < WW)
            v = hbase[((size_t)gy * WW + gx) * CC + c];
        smHalo[f] = v;
    }
    for (int f = tid; f < 2304; f += 256) smCw[f] = conv_w[f];
    __syncthreads();

    // ---- Conv 3x3 (fp32), scatter P into A-frag layout at smActB ----
    {
        const int m  = tid & 63;
        const int og = tid >> 6;          // 4 output channels per thread
        const int ly = m >> 3, lx = m & 7;
        float a0 = 0.f, a1 = 0.f, a2 = 0.f, a3 = 0.f;
        #pragma unroll
        for (int ci = 0; ci < 16; ci++) {
            #pragma unroll
            for (int r = 0; r < 3; r++) {
                #pragma unroll
                for (int s = 0; s < 3; s++) {
                    float hv = smHalo[((ly + s) * 10 + (lx + r)) * 16 + ci];
                    int cb = og * 576 + ci * 9 + r * 3 + s;
                    a0 = fmaf(hv, smCw[cb      ], a0);
                    a1 = fmaf(hv, smCw[cb + 144], a1);
                    a2 = fmaf(hv, smCw[cb + 288], a2);
                    a3 = fmaf(hv, smCw[cb + 432], a3);
                }
            }
        }
        // scatter: element (m, c=og*4+j) -> frag layout [mt][ktile][lane'][slot]
        const int mt = m >> 4;
        const int kt = og >> 1;
        const int rh = (m & 15) >> 3;
        const int slotbase = (og & 1) * 2 + rh;
        float vals[4] = {a0, a1, a2, a3};
        #pragma unroll
        for (int j = 0; j < 4; j++) {
            int lanep = (m & 7) * 4 + j;
            smActB[((mt * 2 + kt) * 32 + lanep) * 4 + slotbase] = tf32r(vals[j]);
        }
    }
    cpa_wait0();       // panel0 + w_first landed
    __syncthreads();   // conv scatter visible; cp.async data visible to all

    // ---- First layer: 16 -> 256 via mma (A = P frags, B = w_first in buf1) ----
    float acc[2][8][4];
    {
        #pragma unroll
        for (int nt = 0; nt < 8; nt++) {
            int n = (n0q * 8 + nt) * 8 + 2 * t;
            float bz0 = b_first[n];
            float bz1 = b_first[n + 1];
            #pragma unroll
            for (int mtl = 0; mtl < 2; mtl++) {
                acc[mtl][nt][0] = bz0; acc[mtl][nt][1] = bz1;
                acc[mtl][nt][2] = bz0; acc[mtl][nt][3] = bz1;
            }
        }
        float4 a[2][2];
        #pragma unroll
        for (int mtl = 0; mtl < 2; mtl++)
            #pragma unroll
            for (int kt = 0; kt < 2; kt++)
                a[mtl][kt] = *(const float4*)(smActB + (((mw * 2 + mtl) * 2 + kt) * 32 + lane) * 4);
        float4 bch[8];
        #pragma unroll
        for (int nt = 0; nt < 8; nt++)
            bch[nt] = *(const float4*)(smWbuf + 8192 + ((n0q * 8 + nt) * 32 + lane) * 4);
        #pragma unroll
        for (int ks2 = 0; ks2 < 2; ks2++)
            #pragma unroll
            for (int mtl = 0; mtl < 2; mtl++)
                #pragma unroll
                for (int nt = 0; nt < 8; nt++)
                    mma8(acc[mtl][nt], a[mtl][ks2],
                         ks2 ? bch[nt].z : bch[nt].x,
                         ks2 ? bch[nt].w : bch[nt].y);
        // epilogue: relu + scatter into smActA (A-frag layout for layer 0)
        #pragma unroll
        for (int mtl = 0; mtl < 2; mtl++) {
            const int mt_g = mw * 2 + mtl;
            #pragma unroll
            for (int nt = 0; nt < 8; nt++) {
                const int ktn = n0q * 8 + nt;
                float* base = smActA + (mt_g * 32 + ktn) * 128;
                #pragma unroll
                for (int rh = 0; rh < 2; rh++)
                    #pragma unroll
                    for (int j = 0; j < 2; j++) {
                        int kk = 2 * t + j;
                        int lanep = g * 4 + (kk & 3);
                        int slot  = (kk >> 2) * 2 + rh;
                        base[lanep * 4 + slot] = tf32r(fmaxf(acc[mtl][nt][rh * 2 + j], 0.f));
                    }
            }
        }
    }

    // ---- 3 interim layers, 8 panels each, double-buffered cp.async ----
    for (int q = 0; q < 24; q++) {
        const int l = q >> 3, p = q & 7, cur = q & 1;
        if (p == 0) {
            #pragma unroll
            for (int nt = 0; nt < 8; nt++) {
                int n = (n0q * 8 + nt) * 8 + 2 * t;
                float bz0 = b_interim[l * HID + n];
                float bz1 = b_interim[l * HID + n + 1];
                #pragma unroll
                for (int mtl = 0; mtl < 2; mtl++) {
                    acc[mtl][nt][0] = bz0; acc[mtl][nt][1] = bz1;
                    acc[mtl][nt][2] = bz0; acc[mtl][nt][3] = bz1;
                }
            }
        }
        cpa_wait0();
        __syncthreads();
        if (q < 23) {
            const float* src = g_wswz + (size_t)(q + 1) * 8192;
            uint32_t dst = smWbuf_u + ((q + 1) & 1) * (8192 * 4);
            #pragma unroll
            for (int i = 0; i < 8; i++)
                cpa16(dst + tid * 128 + i * 16, src + tid * 32 + i * 4);
            cpa_commit();
        } else {
            // prefetch w_last into buf0 (free: panel 23 uses buf1)
            #pragma unroll
            for (int i = 0; i < 4; i++)
                cpa16(smWbuf_u + tid * 64 + i * 16, g_wswz + WSWZ_LAST + tid * 16 + i * 4);
            cpa_commit();
        }

        const float* actIn = (l & 1) ? smActB : smActA;
        const float* wb = smWbuf + cur * 8192;
        #pragma unroll
        for (int kp = 0; kp < 2; kp++) {
            float4 a[2][2];
            #pragma unroll
            for (int mtl = 0; mtl < 2; mtl++)
                #pragma unroll
                for (int kt2 = 0; kt2 < 2; kt2++)
                    a[mtl][kt2] = *(const float4*)(actIn +
                        (((mw * 2 + mtl) * 32 + (p * 4 + kp * 2 + kt2)) * 32 + lane) * 4);
            float4 bch[8];
            #pragma unroll
            for (int nt = 0; nt < 8; nt++)
                bch[nt] = *(const float4*)(wb + (((n0q * 8 + nt) * 2 + kp) * 32 + lane) * 4);
            #pragma unroll
            for (int ks2 = 0; ks2 < 2; ks2++)
                #pragma unroll
                for (int mtl = 0; mtl < 2; mtl++)
                    #pragma unroll
                    for (int nt = 0; nt < 8; nt++)
                        mma8(acc[mtl][nt], a[mtl][ks2],
                             ks2 ? bch[nt].z : bch[nt].x,
                             ks2 ? bch[nt].w : bch[nt].y);
        }

        if (p == 7) {
            // epilogue: relu + scatter into the other act buffer
            float* actOut = (l & 1) ? smActA : smActB;
            #pragma unroll
            for (int mtl = 0; mtl < 2; mtl++) {
                const int mt_g = mw * 2 + mtl;
                #pragma unroll
                for (int nt = 0; nt < 8; nt++) {
                    const int ktn = n0q * 8 + nt;
                    float* base = actOut + (mt_g * 32 + ktn) * 128;
                    #pragma unroll
                    for (int rh = 0; rh < 2; rh++)
                        #pragma unroll
                        for (int j = 0; j < 2; j++) {
                            int kk = 2 * t + j;
                            int lanep = g * 4 + (kk & 3);
                            int slot  = (kk >> 2) * 2 + rh;
                            base[lanep * 4 + slot] = tf32r(fmaxf(acc[mtl][nt][rh * 2 + j], 0.f));
                        }
                }
            }
        }
    }

    cpa_wait0();       // w_last in buf0
    __syncthreads();   // final acts (smActB) visible

    // ---- Last layer: 256 -> 16 via mma + residual + store ----
    {
        const int mt  = wid & 3;       // one 16x8 C tile per warp
        const int ntl = wid >> 2;
        float acc2[4] = {0.f, 0.f, 0.f, 0.f};
        #pragma unroll 2
        for (int p = 0; p < 8; p++) {
            #pragma unroll
            for (int kp = 0; kp < 2; kp++) {
                float4 bch = *(const float4*)(smWbuf + (((p * 2 + ntl) * 2 + kp) * 32 + lane) * 4);
                #pragma unroll
                for (int ks2 = 0; ks2 < 2; ks2++) {
                    int kt = p * 4 + kp * 2 + ks2;
                    float4 a = *(const float4*)(smActB + ((mt * 32 + kt) * 32 + lane) * 4);
                    mma8(acc2, a, ks2 ? bch.z : bch.x, ks2 ? bch.w : bch.y);
                }
            }
        }
        #pragma unroll
        for (int rh = 0; rh < 2; rh++)
            #pragma unroll
            for (int j = 0; j < 2; j++) {
                int kk = 2 * t + j;
                int m  = mt * 16 + rh * 8 + g;
                int ch = ntl * 8 + kk;
                int ly = m >> 3, lx = m & 7;
                int gy = y0 + ly, gx = x0 + lx;
                hout[(((size_t)b * HH + gy) * WW + gx) * CC + ch] =
                    smHalo[((ly + 1) * 10 + (lx + 1)) * 16 + ch] + acc2[rh * 2 + j];
            }
    }
}

__global__ void copy_f4_kernel(const float4* __restrict__ src, float4* __restrict__ dst)
{
    int i = blockIdx.x * blockDim.x + threadIdx.x;
    dst[i] = src[i];
}

extern "C" void kernel_launch(void* const* d_in, const int* in_sizes, int n_in,
                              void* d_out, int out_size)
{
    const float* x         = (const float*)d_in[0];
    const float* conv_w    = (const float*)d_in[1];
    const float* w_first   = (const float*)d_in[2];
    const float* b_first   = (const float*)d_in[3];
    const float* w_interim = (const float*)d_in[4];
    const float* b_interim = (const float*)d_in[5];
    const float* w_last    = (const float*)d_in[6];
    // d_in[7] (steps) unused: fixed at 16.

    float* out  = (float*)d_out;            // x_final
    float* hist = out + NELEM;              // history

    cudaFuncSetAttribute(nca_step_kernel,
                         cudaFuncAttributeMaxDynamicSharedMemorySize, SMEM_BYTES);

    preswizzle_kernel<<<(204800 + 255) / 256, 256>>>(w_interim, w_first, w_last);

    // history[0] = x
    copy_f4_kernel<<<NELEM / 4 / 256, 256>>>((const float4*)x, (float4*)hist);

    dim3 grid(WW / 8, HH / 8, BB);
    for (int tstep = 1; tstep <= STEPS; tstep++) {
        nca_step_kernel<<<grid, 256, SMEM_BYTES>>>(
            hist + (size_t)(tstep - 1) * NELEM,
            hist + (size_t)tstep * NELEM,
            conv_w, b_first, b_interim);
    }

    // x_final = history[STEPS]
    copy_f4_kernel<<<NELEM / 4 / 256, 256>>>(
        (const float4*)(hist + (size_t)STEPS * NELEM), (float4*)out);
}

// round 5
// speedup vs baseline: 4.3629x; 1.4805x over previous
#include <cuda_runtime.h>
#include <cstdint>

// Problem constants
#define BB 8
#define HH 128
#define WW 128
#define CC 16
#define HID 256
#define NL 3
#define STEPS 16
#define NELEM (BB*HH*WW*CC)   // 2,097,152

// SMEM layout (floats). CTA tile: 8 rows (y) x 16 cols (x) = 128 cells (M=128).
#define OFF_HALO 0            // channel-major halo: 16ch * 10y * 18x = 2880
#define OFF_CW   2880         // transposed conv w: [ci*9+rs][16 o] = 2304
#define OFF_P    5184         // P frags: 8mt * 2kt * 32 * 4 = 2048
#define OFF_ACT  7232         // acts (frag layout): 8mt * 32kt * 32 * 4 = 32768
#define OFF_WBUF 40000        // 2 * 8192 double-buffered weight panel
#define SMEM_FLOATS 56384
#define SMEM_BYTES (SMEM_FLOATS*4)   // 225,536 B

// Pre-swizzled weights in gmem (written once per launch)
#define WSWZ_FIRST 196608     // interim: 24 panels * 8192
#define WSWZ_LAST  200704
__device__ float g_wswz[204800];

__device__ __forceinline__ float tf32r(float x) {
    uint32_t u;
    asm("cvt.rna.tf32.f32 %0, %1;" : "=r"(u) : "f"(x));
    return __uint_as_float(u);
}

__device__ __forceinline__ void mma8(float* c, const float4& a, float b0, float b1) {
    asm volatile(
        "mma.sync.aligned.m16n8k8.row.col.f32.tf32.tf32.f32 "
        "{%0,%1,%2,%3}, {%4,%5,%6,%7}, {%8,%9}, {%0,%1,%2,%3};\n"
        : "+f"(c[0]), "+f"(c[1]), "+f"(c[2]), "+f"(c[3])
        : "r"(__float_as_uint(a.x)), "r"(__float_as_uint(a.y)),
          "r"(__float_as_uint(a.z)), "r"(__float_as_uint(a.w)),
          "r"(__float_as_uint(b0)),  "r"(__float_as_uint(b1)));
}

__device__ __forceinline__ void cpa16(uint32_t dst, const float* src) {
    asm volatile("cp.async.cg.shared.global [%0], [%1], 16;\n" :: "r"(dst), "l"(src));
}
__device__ __forceinline__ void cpa_commit() { asm volatile("cp.async.commit_group;\n" ::: "memory"); }
__device__ __forceinline__ void cpa_wait0()  { asm volatile("cp.async.wait_group 0;\n"  ::: "memory"); }

// ---------------- Pre-swizzle weights into mma fragment order (tf32) -------------
// interim: idx = ((((l*8+p)*32+nt)*2+kp)*32+lane)*4 + slot
//   value = W_l[n][k], n = nt*8+g, k = p*32 + kp*16 + t + 4*(slot&1) + 8*(slot>>1)
// first:   idx = WSWZ_FIRST + ((nt*32+lane)*4 + slot), k over 16
// last:    idx = WSWZ_LAST  + ((((p*2+ntl)*2+kp)*32+lane)*4 + slot)
__global__ void preswizzle_kernel(const float* __restrict__ wi,
                                  const float* __restrict__ wf,
                                  const float* __restrict__ wl)
{
    int idx = blockIdx.x * blockDim.x + threadIdx.x;
    if (idx >= 204800) return;
    if (idx < WSWZ_FIRST) {
        int slot = idx & 3, lane = (idx >> 2) & 31, kp = (idx >> 7) & 1;
        int nt = (idx >> 8) & 31, p = (idx >> 13) & 7, l = idx >> 16;
        int g = lane >> 2, t = lane & 3;
        int n = nt * 8 + g;
        int k = p * 32 + kp * 16 + t + 4 * (slot & 1) + 8 * (slot >> 1);
        g_wswz[idx] = tf32r(wi[(l * HID + n) * HID + k]);
    } else if (idx < WSWZ_LAST) {
        int j = idx - WSWZ_FIRST;
        int slot = j & 3, lane = (j >> 2) & 31, nt = (j >> 7) & 31;
        int g = lane >> 2, t = lane & 3;
        int n = nt * 8 + g;
        int k = t + 4 * (slot & 1) + 8 * (slot >> 1);
        g_wswz[idx] = tf32r(wf[n * CC + k]);
    } else {
        int j = idx - WSWZ_LAST;
        int slot = j & 3, lane = (j >> 2) & 31, kp = (j >> 7) & 1;
        int ntl = (j >> 8) & 1, p = (j >> 9) & 7;
        int g = lane >> 2, t = lane & 3;
        int n = ntl * 8 + g;
        int k = p * 32 + kp * 16 + t + 4 * (slot & 1) + 8 * (slot >> 1);
        g_wswz[idx] = tf32r(wl[n * HID + k]);
    }
}

// ---------------- Fused NCA step: M=128 cells per CTA, 256 threads ----------------
__global__ __launch_bounds__(256, 1)
void nca_step_kernel(const float* __restrict__ hin, float* __restrict__ hout,
                     const float* __restrict__ conv_w,
                     const float* __restrict__ b_first,
                     const float* __restrict__ b_interim)
{
    extern __shared__ float sm[];
    float* smHalo = sm + OFF_HALO;
    float* smCwT  = sm + OFF_CW;
    float* smP    = sm + OFF_P;
    float* smAct  = sm + OFF_ACT;
    float* smWbuf = sm + OFF_WBUF;
    const uint32_t smWbuf_u = (uint32_t)__cvta_generic_to_shared(smWbuf);

    const int tid  = threadIdx.x;
    const int lane = tid & 31;
    const int wid  = tid >> 5;
    const int g = lane >> 2;
    const int t = lane & 3;
    const int mw  = wid & 1;        // warp m-half: 4 m16-tiles each (M=128)
    const int n0q = wid >> 1;       // warp n-quarter: 8 n8-tiles each (N=256)

    const int x0 = blockIdx.x * 16;
    const int y0 = blockIdx.y * 8;
    const int b  = blockIdx.z;
    const float* hbase = hin + (size_t)b * HH * WW * CC;

    // ---- Prologue prefetch: interim panel 0 -> buf0; w_first -> buf1 ----
    #pragma unroll
    for (int i = 0; i < 8; i++)
        cpa16(smWbuf_u + tid * 128 + i * 16, g_wswz + tid * 32 + i * 4);
    cpa_commit();
    #pragma unroll
    for (int i = 0; i < 4; i++)
        cpa16(smWbuf_u + 8192 * 4 + tid * 64 + i * 16, g_wswz + WSWZ_FIRST + tid * 16 + i * 4);
    cpa_commit();

    // ---- Halo (channel-major [c][y 10][x 18], zero padded) ----
    for (int f = tid; f < 2880; f += 256) {
        int xx = f % 18;
        int yy = (f / 18) % 10;
        int c  = f / 180;
        int gx = x0 - 1 + xx;
        int gy = y0 - 1 + yy;
        float v = 0.f;
        if (gy >= 0 && gy < HH && gx >= 0 && gx < WW)
            v = hbase[((size_t)gy * WW + gx) * CC + c];
        smHalo[f] = v;
    }
    // conv weights transposed: smCwT[(ci*9+rs)*16 + o]
    for (int f = tid; f < 2304; f += 256)
        smCwT[f] = conv_w[(f & 15) * 144 + (f >> 4)];
    __syncthreads();

    // ---- Conv 3x3 (fp32): thread = (cell m = tid&127, channel group og = tid>>7) ----
    {
        const int m  = tid & 127;
        const int og = tid >> 7;          // 8 output channels per thread
        const int ly = m >> 4, lx = m & 15;
        float a8[8] = {0.f,0.f,0.f,0.f,0.f,0.f,0.f,0.f};
        #pragma unroll
        for (int ci = 0; ci < 16; ci++) {
            #pragma unroll
            for (int r = 0; r < 3; r++) {
                #pragma unroll
                for (int s = 0; s < 3; s++) {
                    float hv = smHalo[ci * 180 + (ly + s) * 18 + (lx + r)];
                    const float* wp = smCwT + (ci * 9 + r * 3 + s) * 16 + og * 8;
                    float4 w0 = *(const float4*)(wp);
                    float4 w1 = *(const float4*)(wp + 4);
                    a8[0] = fmaf(hv, w0.x, a8[0]); a8[1] = fmaf(hv, w0.y, a8[1]);
                    a8[2] = fmaf(hv, w0.z, a8[2]); a8[3] = fmaf(hv, w0.w, a8[3]);
                    a8[4] = fmaf(hv, w1.x, a8[4]); a8[5] = fmaf(hv, w1.y, a8[5]);
                    a8[6] = fmaf(hv, w1.z, a8[6]); a8[7] = fmaf(hv, w1.w, a8[7]);
                }
            }
        }
        // scatter P into A-frag layout: tile(mt = m>>4, kt = og), row r = m&15, k = j
        const int mt = m >> 4;
        const int rh = (m >> 3) & 1;
        const int lanebase = (m & 7) * 4;
        #pragma unroll
        for (int j = 0; j < 8; j++) {
            int lanep = lanebase + (j & 3);
            int slot  = (j >> 2) * 2 + rh;
            smP[((mt * 2 + og) * 32 + lanep) * 4 + slot] = tf32r(a8[j]);
        }
    }
    cpa_wait0();       // panel0 + w_first landed
    __syncthreads();   // P visible to all

    // ---- First layer: 16 -> 256 via mma ----
    float acc[4][8][4];
    {
        #pragma unroll
        for (int nt = 0; nt < 8; nt++) {
            int n = (n0q * 8 + nt) * 8 + 2 * t;
            float bz0 = b_first[n];
            float bz1 = b_first[n + 1];
            #pragma unroll
            for (int mtl = 0; mtl < 4; mtl++) {
                acc[mtl][nt][0] = bz0; acc[mtl][nt][1] = bz1;
                acc[mtl][nt][2] = bz0; acc[mtl][nt][3] = bz1;
            }
        }
        float4 af[4][2];
        #pragma unroll
        for (int mtl = 0; mtl < 4; mtl++)
            #pragma unroll
            for (int kt = 0; kt < 2; kt++)
                af[mtl][kt] = *(const float4*)(smP + (((mw * 4 + mtl) * 2 + kt) * 32 + lane) * 4);
        float4 bch[8];
        #pragma unroll
        for (int nt = 0; nt < 8; nt++)
            bch[nt] = *(const float4*)(smWbuf + 8192 + ((n0q * 8 + nt) * 32 + lane) * 4);
        #pragma unroll
        for (int ks2 = 0; ks2 < 2; ks2++)
            #pragma unroll
            for (int mtl = 0; mtl < 4; mtl++)
                #pragma unroll
                for (int nt = 0; nt < 8; nt++)
                    mma8(acc[mtl][nt], af[mtl][ks2],
                         ks2 ? bch[nt].z : bch[nt].x,
                         ks2 ? bch[nt].w : bch[nt].y);
        // epilogue: relu + scatter into smAct (nobody has read smAct yet; no sync needed)
        #pragma unroll
        for (int mtl = 0; mtl < 4; mtl++) {
            const int mt_g = mw * 4 + mtl;
            #pragma unroll
            for (int nt = 0; nt < 8; nt++) {
                float* base = smAct + (mt_g * 32 + (n0q * 8 + nt)) * 128;
                #pragma unroll
                for (int rh = 0; rh < 2; rh++)
                    #pragma unroll
                    for (int j = 0; j < 2; j++) {
                        int kk = 2 * t + j;
                        base[(g * 4 + (kk & 3)) * 4 + (kk >> 2) * 2 + rh] =
                            tf32r(fmaxf(acc[mtl][nt][rh * 2 + j], 0.f));
                    }
            }
        }
    }

    // ---- 3 interim layers: 24 k-panels, one sync per panel, reg accumulation ----
    #pragma unroll 1
    for (int q = 0; q < 24; q++) {
        const int l = q >> 3, p = q & 7;
        cpa_wait0();        // buf[q&1] holds panel q
        __syncthreads();    // everyone done with buf[(q-1)&1] + (at p==0) prev epilogue visible
        if (q < 23) {
            const float* src = g_wswz + (size_t)(q + 1) * 8192;
            uint32_t dst = smWbuf_u + ((q + 1) & 1) * (8192 * 4);
            #pragma unroll
            for (int i = 0; i < 8; i++)
                cpa16(dst + tid * 128 + i * 16, src + tid * 32 + i * 4);
            cpa_commit();
        } else {
            #pragma unroll
            for (int i = 0; i < 4; i++)
                cpa16(smWbuf_u + tid * 64 + i * 16, g_wswz + WSWZ_LAST + tid * 16 + i * 4);
            cpa_commit();
        }

        if (p == 0) {
            #pragma unroll
            for (int nt = 0; nt < 8; nt++) {
                int n = (n0q * 8 + nt) * 8 + 2 * t;
                float bz0 = b_interim[l * HID + n];
                float bz1 = b_interim[l * HID + n + 1];
                #pragma unroll
                for (int mtl = 0; mtl < 4; mtl++) {
                    acc[mtl][nt][0] = bz0; acc[mtl][nt][1] = bz1;
                    acc[mtl][nt][2] = bz0; acc[mtl][nt][3] = bz1;
                }
            }
        }

        const float* wb = smWbuf + (q & 1) * 8192;
        #pragma unroll
        for (int kp = 0; kp < 2; kp++) {
            float4 bch[8];
            #pragma unroll
            for (int nt = 0; nt < 8; nt++)
                bch[nt] = *(const float4*)(wb + (((n0q * 8 + nt) * 2 + kp) * 32 + lane) * 4);
            #pragma unroll
            for (int ks2 = 0; ks2 < 2; ks2++) {
                float4 af[4];
                #pragma unroll
                for (int mtl = 0; mtl < 4; mtl++)
                    af[mtl] = *(const float4*)(smAct +
                        (((mw * 4 + mtl) * 32 + (p * 4 + kp * 2 + ks2)) * 32 + lane) * 4);
                #pragma unroll
                for (int mtl = 0; mtl < 4; mtl++)
                    #pragma unroll
                    for (int nt = 0; nt < 8; nt++)
                        mma8(acc[mtl][nt], af[mtl],
                             ks2 ? bch[nt].z : bch[nt].x,
                             ks2 ? bch[nt].w : bch[nt].y);
            }
        }

        if (p == 7) {
            __syncthreads();   // all warps done READING smAct for this layer
            #pragma unroll
            for (int mtl = 0; mtl < 4; mtl++) {
                const int mt_g = mw * 4 + mtl;
                #pragma unroll
                for (int nt = 0; nt < 8; nt++) {
                    float* base = smAct + (mt_g * 32 + (n0q * 8 + nt)) * 128;
                    #pragma unroll
                    for (int rh = 0; rh < 2; rh++)
                        #pragma unroll
                        for (int j = 0; j < 2; j++) {
                            int kk = 2 * t + j;
                            base[(g * 4 + (kk & 3)) * 4 + (kk >> 2) * 2 + rh] =
                                tf32r(fmaxf(acc[mtl][nt][rh * 2 + j], 0.f));
                        }
                }
            }
        }
    }

    cpa_wait0();       // w_last in buf0
    __syncthreads();   // final acts visible

    // ---- Last layer: 256 -> 16 via mma + residual + store. Warp = m16 tile wid. ----
    {
        const int mt = wid;
        float acc2[2][4] = {{0.f,0.f,0.f,0.f},{0.f,0.f,0.f,0.f}};
        #pragma unroll 2
        for (int p = 0; p < 8; p++) {
            #pragma unroll
            for (int kp = 0; kp < 2; kp++) {
                float4 b0 = *(const float4*)(smWbuf + (((p * 2 + 0) * 2 + kp) * 32 + lane) * 4);
                float4 b1 = *(const float4*)(smWbuf + (((p * 2 + 1) * 2 + kp) * 32 + lane) * 4);
                #pragma unroll
                for (int ks2 = 0; ks2 < 2; ks2++) {
                    float4 a = *(const float4*)(smAct +
                        ((mt * 32 + (p * 4 + kp * 2 + ks2)) * 32 + lane) * 4);
                    mma8(acc2[0], a, ks2 ? b0.z : b0.x, ks2 ? b0.w : b0.y);
                    mma8(acc2[1], a, ks2 ? b1.z : b1.x, ks2 ? b1.w : b1.y);
                }
            }
        }
        #pragma unroll
        for (int ntl = 0; ntl < 2; ntl++)
            #pragma unroll
            for (int rh = 0; rh < 2; rh++)
                #pragma unroll
                for (int j = 0; j < 2; j++) {
                    int ch = ntl * 8 + 2 * t + j;
                    int m  = mt * 16 + rh * 8 + g;
                    int ly = m >> 4, lx = m & 15;
                    hout[(((size_t)b * HH + (y0 + ly)) * WW + (x0 + lx)) * CC + ch] =
                        smHalo[ch * 180 + (ly + 1) * 18 + (lx + 1)] + acc2[ntl][rh * 2 + j];
                }
    }
}

__global__ void copy_f4_kernel(const float4* __restrict__ src, float4* __restrict__ dst)
{
    int i = blockIdx.x * blockDim.x + threadIdx.x;
    dst[i] = src[i];
}

extern "C" void kernel_launch(void* const* d_in, const int* in_sizes, int n_in,
                              void* d_out, int out_size)
{
    const float* x         = (const float*)d_in[0];
    const float* conv_w    = (const float*)d_in[1];
    const float* w_first   = (const float*)d_in[2];
    const float* b_first   = (const float*)d_in[3];
    const float* w_interim = (const float*)d_in[4];
    const float* b_interim = (const float*)d_in[5];
    const float* w_last    = (const float*)d_in[6];
    // d_in[7] (steps) unused: fixed at 16.

    float* out  = (float*)d_out;            // x_final
    float* hist = out + NELEM;              // history

    cudaFuncSetAttribute(nca_step_kernel,
                         cudaFuncAttributeMaxDynamicSharedMemorySize, SMEM_BYTES);

    preswizzle_kernel<<<(204800 + 255) / 256, 256>>>(w_interim, w_first, w_last);

    // history[0] = x
    copy_f4_kernel<<<NELEM / 4 / 256, 256>>>((const float4*)x, (float4*)hist);

    dim3 grid(WW / 16, HH / 8, BB);
    for (int tstep = 1; tstep <= STEPS; tstep++) {
        nca_step_kernel<<<grid, 256, SMEM_BYTES>>>(
            hist + (size_t)(tstep - 1) * NELEM,
            hist + (size_t)tstep * NELEM,
            conv_w, b_first, b_interim);
    }

    // x_final = history[STEPS]
    copy_f4_kernel<<<NELEM / 4 / 256, 256>>>(
        (const float4*)(hist + (size_t)STEPS * NELEM), (float4*)out);
}